// round 2
// baseline (speedup 1.0000x reference)
#include <cuda_runtime.h>
#include <math.h>

#define NUMS  128
#define BATCH 256
#define HCH   64
#define DIM   32
#define HID   256
#define XDIM  65
#define KW    32
#define DT    (1.0f/128.0f)
#define GRID  132
#define TPB   512

// ---------------- device scratch ----------------
__device__ float d_gvals[NUMS + 1];
__device__ float d_kmu[NUMS + 1];
__device__ float d_ksig[NUMS + 1];
__device__ float d_H[BATCH * 512];              // [b][0:256)=mu hidden, [256:512)=sig hidden
__device__ float d_muh[NUMS * BATCH * HCH];     // mu history
__device__ float d_svh[NUMS * BATCH * HCH];     // sv history
__device__ unsigned d_bar;

// ---------------- init: kernel MLPs over t grid + barrier reset ----------------
__global__ void init_kernel(const float* gw1, const float* gb1, const float* gw2, const float* gb2,
                            const float* mw1, const float* mb1, const float* mw2, const float* mb2,
                            const float* sw1, const float* sb1, const float* sw2, const float* sb2)
{
    int t = threadIdx.x;
    if (t == 0) d_bar = 0u;
    if (t <= NUMS) {
        float tt = t * DT;
        float a = gb2[0], b = mb2[0], c = sb2[0];
        for (int k = 0; k < KW; ++k) {
            a += tanhf(tt * gw1[k] + gb1[k]) * gw2[k];
            b += tanhf(tt * mw1[k] + mb1[k]) * mw2[k];
            c += tanhf(tt * sw1[k] + sb1[k]) * sw2[k];
        }
        d_gvals[t] = a; d_kmu[t] = b; d_ksig[t] = c;
    }
}

// ---------------- grid-wide software barrier (all 132 blocks resident) ----------------
__device__ __forceinline__ void gbar(unsigned target)
{
    __threadfence();
    __syncthreads();
    if (threadIdx.x == 0) {
        atomicAdd(&d_bar, 1u);
        while (*((volatile unsigned*)&d_bar) < target) { }
        __threadfence();
    }
    __syncthreads();
}

// ---------------- persistent solver ----------------
__global__ void __launch_bounds__(TPB, 1) solve(
    const float* __restrict__ Bin, const float* __restrict__ z0,
    const float* __restrict__ muw1, const float* __restrict__ mub1,
    const float* __restrict__ muw2, const float* __restrict__ mub2,
    const float* __restrict__ sgw1, const float* __restrict__ sgb1,
    const float* __restrict__ sgw2, const float* __restrict__ sgb2,
    float* __restrict__ out)
{
    __shared__ float kwv[NUMS], ksv[NUMS];
    __shared__ float red[TPB];
    __shared__ float xs[2][XDIM];
    __shared__ float Hs[64][33];
    __shared__ __align__(16) float Ws[32][68];
    __shared__ __align__(16) float dBs[64][32];

    int bk = blockIdx.x, t = threadIdx.x;
    unsigned target = 0;

    // GEMM tile mapping (fixed per block): 128 sig tiles (4 batch x 32 col), 4 mu tiles
    bool is_mu = (bk >= 128);
    int b0g  = is_mu ? (bk - 128) * 64 : (bk >> 5) * 64;
    int cb   = is_mu ? 0 : (bk & 31);
    int col0 = cb * 64;
    int hofs = is_mu ? 0 : 256;
    const float* W2 = is_mu ? muw2 : sgw2;
    int ldw = is_mu ? HCH : HCH * DIM;

    int convb0 = bk * 2;   // conv blocks 0..127 each handle 2 batch rows

    for (int j = 0; j < NUMS; ++j) {
        // ---------- phase 1: Volterra conv -> S_j, then first-layer MLPs ----------
        if (bk < 128) {
            if (t < j) { kwv[t] = DT * d_kmu[j - t]; ksv[t] = d_ksig[j - t]; }
            if (t < 2) xs[t][0] = j * DT;
            __syncthreads();

            int e = t & 127, p = t >> 7;
            float acc = 0.f;
            int base = convb0 * HCH + e;
            #pragma unroll 2
            for (int m = p; m < j; m += 4)
                acc += kwv[m] * d_muh[m * (BATCH * HCH) + base]
                     + ksv[m] * d_svh[m * (BATCH * HCH) + base];
            red[t] = acc;
            __syncthreads();

            if (t < 128) {
                float s = red[t] + red[t + 128] + red[t + 256] + red[t + 384];
                float z = z0[convb0 * HCH + t];
                float S = z * d_gvals[j] + s;
                out[(size_t)j * (BATCH * HCH) + convb0 * HCH + t] = S;
                xs[t >> 6][1 + (t & 63)] = (j == 0) ? z : S;
            }
            __syncthreads();

            // MLP1: 2 rows x 512 combined hidden cols; thread -> (row, 2 cols)
            int r  = t >> 8, ci = t & 255;
            const float* w1; const float* b1; int c0;
            if (ci < 128) { w1 = muw1; b1 = mub1; c0 = ci * 2; }
            else          { w1 = sgw1; b1 = sgb1; c0 = (ci - 128) * 2; }
            float ax = b1[c0], ay = b1[c0 + 1];
            #pragma unroll 5
            for (int i = 0; i < XDIM; ++i) {
                float2 w = *(const float2*)&w1[i * HID + c0];
                float xv = xs[r][i];
                ax += xv * w.x; ay += xv * w.y;
            }
            int gc = ci * 2;
            d_H[(convb0 + r) * 512 + gc]     = tanhf(ax);
            d_H[(convb0 + r) * 512 + gc + 1] = tanhf(ay);
        }
        gbar(target += GRID);

        // ---------- phase 2: second-layer GEMMs (64x64 tile, K=256, f32x2) ----------
        {
            if (!is_mu) {
                int rr = t >> 3, c = (t & 7) * 4;
                const float* src = &Bin[(size_t)(b0g + rr) * ((NUMS + 1) * DIM)
                                        + (size_t)(j + 1) * DIM + c];
                float4 v = *(const float4*)src;
                if (j > 0) {
                    float4 u = *(const float4*)(src - DIM);
                    v.x -= u.x; v.y -= u.y; v.z -= u.z; v.w -= u.w;
                }
                *(float4*)&dBs[rr][c] = v;
            }

            int r = t >> 3, cg8 = (t & 7) * 8;
            unsigned long long acc2[4] = {0ull, 0ull, 0ull, 0ull};

            for (int kc = 0; kc < 8; ++kc) {
                __syncthreads();
                {   // H tile [64 x 32], L2-coherent read (rewritten every step by other SMs)
                    int r2 = t >> 3, c = (t & 7) * 4;
                    float4 v = __ldcg((const float4*)&d_H[(b0g + r2) * 512 + hofs + kc * 32 + c]);
                    Hs[r2][c] = v.x; Hs[r2][c + 1] = v.y; Hs[r2][c + 2] = v.z; Hs[r2][c + 3] = v.w;
                }
                {   // W tile [32 x 64], read-only, L1-resident across steps
                    int kr = t >> 4, c = (t & 15) * 4;
                    float4 v = *(const float4*)&W2[(size_t)(kc * 32 + kr) * ldw + col0 + c];
                    Ws[kr][c] = v.x; Ws[kr][c + 1] = v.y; Ws[kr][c + 2] = v.z; Ws[kr][c + 3] = v.w;
                }
                __syncthreads();
                #pragma unroll
                for (int kk = 0; kk < 32; ++kk) {
                    float a = Hs[r][kk];
                    unsigned long long a2;
                    asm("mov.b64 %0, {%1, %1};" : "=l"(a2) : "f"(a));
                    const unsigned long long* wp = (const unsigned long long*)&Ws[kk][cg8];
                    #pragma unroll
                    for (int q = 0; q < 4; ++q)
                        asm("fma.rn.f32x2 %0, %1, %2, %3;"
                            : "=l"(acc2[q]) : "l"(a2), "l"(wp[q]), "l"(acc2[q]));
                }
            }

            float C[8];
            asm("mov.b64 {%0, %1}, %2;" : "=f"(C[0]), "=f"(C[1]) : "l"(acc2[0]));
            asm("mov.b64 {%0, %1}, %2;" : "=f"(C[2]), "=f"(C[3]) : "l"(acc2[1]));
            asm("mov.b64 {%0, %1}, %2;" : "=f"(C[4]), "=f"(C[5]) : "l"(acc2[2]));
            asm("mov.b64 {%0, %1}, %2;" : "=f"(C[6]), "=f"(C[7]) : "l"(acc2[3]));

            if (is_mu) {
                #pragma unroll
                for (int q = 0; q < 8; ++q)
                    d_muh[(size_t)j * (BATCH * HCH) + (b0g + r) * HCH + cg8 + q]
                        = C[q] + mub2[cg8 + q];
            } else {
                int dof = cg8 & 31;
                float s = 0.f;
                #pragma unroll
                for (int q = 0; q < 8; ++q)
                    s += (C[q] + sgb2[col0 + cg8 + q]) * dBs[r][dof + q];
                s += __shfl_xor_sync(0xffffffffu, s, 1);
                s += __shfl_xor_sync(0xffffffffu, s, 2);
                if ((t & 3) == 0)
                    d_svh[(size_t)j * (BATCH * HCH) + (b0g + r) * HCH + cb * 2 + ((t >> 2) & 1)] = s;
            }
        }
        gbar(target += GRID);
    }

    // ---------- final output row 128 (conv only) ----------
    if (bk < 128) {
        if (t < NUMS) { kwv[t] = DT * d_kmu[NUMS - t]; ksv[t] = d_ksig[NUMS - t]; }
        __syncthreads();
        int e = t & 127, p = t >> 7;
        float acc = 0.f;
        int base = convb0 * HCH + e;
        #pragma unroll 2
        for (int m = p; m < NUMS; m += 4)
            acc += kwv[m] * d_muh[m * (BATCH * HCH) + base]
                 + ksv[m] * d_svh[m * (BATCH * HCH) + base];
        red[t] = acc;
        __syncthreads();
        if (t < 128) {
            float s = red[t] + red[t + 128] + red[t + 256] + red[t + 384];
            float z = z0[convb0 * HCH + t];
            out[(size_t)NUMS * (BATCH * HCH) + convb0 * HCH + t] = z * d_gvals[NUMS] + s;
        }
    }
}

// ---------------- launch ----------------
extern "C" void kernel_launch(void* const* d_in, const int* in_sizes, int n_in,
                              void* d_out, int out_size)
{
    const float* B    = (const float*)d_in[0];
    const float* z0   = (const float*)d_in[1];
    const float* gw1  = (const float*)d_in[6];
    const float* gb1  = (const float*)d_in[7];
    const float* gw2  = (const float*)d_in[8];
    const float* gb2  = (const float*)d_in[9];
    const float* kmw1 = (const float*)d_in[10];
    const float* kmb1 = (const float*)d_in[11];
    const float* kmw2 = (const float*)d_in[12];
    const float* kmb2 = (const float*)d_in[13];
    const float* ksw1 = (const float*)d_in[14];
    const float* ksb1 = (const float*)d_in[15];
    const float* ksw2 = (const float*)d_in[16];
    const float* ksb2 = (const float*)d_in[17];
    const float* muw1 = (const float*)d_in[18];
    const float* mub1 = (const float*)d_in[19];
    const float* muw2 = (const float*)d_in[20];
    const float* mub2 = (const float*)d_in[21];
    const float* sgw1 = (const float*)d_in[22];
    const float* sgb1 = (const float*)d_in[23];
    const float* sgw2 = (const float*)d_in[24];
    const float* sgb2 = (const float*)d_in[25];
    float* out = (float*)d_out;

    init_kernel<<<1, 256>>>(gw1, gb1, gw2, gb2, kmw1, kmb1, kmw2, kmb2,
                            ksw1, ksb1, ksw2, ksb2);
    solve<<<GRID, TPB>>>(B, z0, muw1, mub1, muw2, mub2,
                         sgw1, sgb1, sgw2, sgb2, out);
}

// round 3
// speedup vs baseline: 2.4809x; 2.4809x over previous
#include <cuda_runtime.h>
#include <math.h>

#define NUMS  128
#define BATCH 256
#define HCH   64
#define DIM   32
#define HID   256
#define XDIM  65
#define KW    32
#define DT    (1.0f/128.0f)
#define GRID  132
#define TPB   256
#define WT    68          // Ws smem row stride (floats)
#define HT    66          // HsT smem row stride (floats)
#define SMEM_FLOATS (HID*WT + HID*HT + 64*36 + 128 + 128 + 256 + 2*65)

typedef unsigned long long ull;

// ---------------- device scratch ----------------
__device__ float d_gvals[NUMS + 1];
__device__ float d_kmu[NUMS + 1];
__device__ float d_ksig[NUMS + 1];
__device__ float d_H[BATCH * 512];              // [b][0:256)=mu hidden, [256:512)=sig hidden
__device__ float d_muh[NUMS * BATCH * HCH];
__device__ float d_svh[NUMS * BATCH * HCH];
__device__ unsigned d_bar;

// ---------------- init ----------------
__global__ void init_kernel(const float* gw1, const float* gb1, const float* gw2, const float* gb2,
                            const float* mw1, const float* mb1, const float* mw2, const float* mb2,
                            const float* sw1, const float* sb1, const float* sw2, const float* sb2)
{
    int t = threadIdx.x;
    if (t == 0) d_bar = 0u;
    if (t <= NUMS) {
        float tt = t * DT;
        float a = gb2[0], b = mb2[0], c = sb2[0];
        for (int k = 0; k < KW; ++k) {
            a += tanhf(tt * gw1[k] + gb1[k]) * gw2[k];
            b += tanhf(tt * mw1[k] + mb1[k]) * mw2[k];
            c += tanhf(tt * sw1[k] + sb1[k]) * sw2[k];
        }
        d_gvals[t] = a; d_kmu[t] = b; d_ksig[t] = c;
    }
}

// ---------------- GPU-scope grid barrier (no sys-scope traffic) ----------------
__device__ __forceinline__ void gbar(unsigned target)
{
    __syncthreads();
    if (threadIdx.x == 0) {
        unsigned* p = &d_bar;
        asm volatile("red.release.gpu.global.add.u32 [%0], 1;" :: "l"(p) : "memory");
        unsigned v;
        do {
            asm volatile("ld.acquire.gpu.global.u32 %0, [%1];" : "=r"(v) : "l"(p) : "memory");
        } while ((int)(v - target) < 0);
    }
    __syncthreads();
}

__device__ __forceinline__ void fma2(ull& acc, ull a, ull b)
{
    asm("fma.rn.f32x2 %0, %1, %2, %3;" : "=l"(acc) : "l"(a), "l"(b), "l"(acc));
}

// ---------------- persistent solver ----------------
__global__ void __launch_bounds__(TPB, 1) solve(
    const float* __restrict__ Bin, const float* __restrict__ z0,
    const float* __restrict__ muw1, const float* __restrict__ mub1,
    const float* __restrict__ muw2, const float* __restrict__ mub2,
    const float* __restrict__ sgw1, const float* __restrict__ sgb1,
    const float* __restrict__ sgw2, const float* __restrict__ sgb2,
    float* __restrict__ out)
{
    extern __shared__ __align__(16) float sm[];
    float* WsS  = sm;                       // [256][WT]
    float* HsT  = WsS + HID * WT;           // [256][HT]  (transposed H tile)
    float* dBsS = HsT + HID * HT;           // [64][36]
    float* kwv  = dBsS + 64 * 36;           // [128]
    float* ksv  = kwv + 128;                // [128]
    float* red  = ksv + 128;                // [256]
    float* xs   = red + 256;                // [2][65]

    int bk = blockIdx.x, t = threadIdx.x;
    unsigned target = 0;

    // GEMM tile mapping
    bool is_mu = (bk >= 128);
    int b0g  = is_mu ? (bk - 128) * 64 : (bk >> 5) * 64;
    int cb   = is_mu ? 0 : (bk & 31);
    int col0 = is_mu ? 0 : cb * 64;
    int hofs = is_mu ? 0 : 256;
    const float* W2 = is_mu ? muw2 : sgw2;
    const float* B2 = is_mu ? mub2 : sgb2;
    int ldw = is_mu ? HCH : HCH * DIM;

    int convb0 = bk * 2;

    // thread tile: warp grid 4(rows)x2(cols), lane grid 8(rows)x4(cols), tile 2x8
    int w  = t >> 5, lane = t & 31;
    int wr = w & 3,  wc = w >> 2;
    int lr = lane >> 2, lc = lane & 3;
    int r0 = wr * 16 + lr * 2;
    int c0 = wc * 32 + lc * 8;

    // ---- load W2 slice into smem once (step-invariant) ----
    for (int idx = t; idx < HID * 16; idx += TPB) {
        int row = idx >> 4, c4 = (idx & 15) * 4;
        float4 v = *(const float4*)&W2[(size_t)row * ldw + col0 + c4];
        *(float4*)&WsS[row * WT + c4] = v;
    }
    // per-thread bias for 8 cols (constant across steps)
    float4 bs0 = *(const float4*)&B2[col0 + c0];
    float4 bs1 = *(const float4*)&B2[col0 + c0 + 4];

    for (int j = 0; j < NUMS; ++j) {
        // ========== phase 1: conv -> S_j, MLP1 -> d_H ==========
        if (bk < 128) {
            if (t < j) { kwv[t] = DT * d_kmu[j - t]; ksv[t] = d_ksig[j - t]; }
            if (t < 2) xs[t * XDIM] = j * DT;
            __syncthreads();

            int e = t & 127, p = t >> 7;
            float acc = 0.f;
            int base = convb0 * HCH + e;
            #pragma unroll 4
            for (int m = p; m < j; m += 2)
                acc += kwv[m] * d_muh[m * (BATCH * HCH) + base]
                     + ksv[m] * d_svh[m * (BATCH * HCH) + base];
            red[t] = acc;
            __syncthreads();

            if (t < 128) {
                float s = red[t] + red[t + 128];
                float z = z0[convb0 * HCH + t];
                float S = z * d_gvals[j] + s;
                out[(size_t)j * (BATCH * HCH) + convb0 * HCH + t] = S;
                xs[(t >> 6) * XDIM + 1 + (t & 63)] = (j == 0) ? z : S;
            }
            __syncthreads();

            // MLP1: thread -> row r (0/1), 4 cols of combined 512 hidden
            int r = t >> 7, ci = t & 127, c4 = ci * 4;
            const float* w1; const float* b1; int cc;
            if (c4 < 256) { w1 = muw1; b1 = mub1; cc = c4; }
            else          { w1 = sgw1; b1 = sgb1; cc = c4 - 256; }
            float4 a = *(const float4*)&b1[cc];
            #pragma unroll 5
            for (int i = 0; i < XDIM; ++i) {
                float4 wv = *(const float4*)&w1[i * HID + cc];
                float xv = xs[r * XDIM + i];
                a.x += xv * wv.x; a.y += xv * wv.y; a.z += xv * wv.z; a.w += xv * wv.w;
            }
            float4 hv = make_float4(tanhf(a.x), tanhf(a.y), tanhf(a.z), tanhf(a.w));
            *(float4*)&d_H[(convb0 + r) * 512 + c4] = hv;
        }
        gbar(target += GRID);

        // ========== phase 2: second-layer GEMM (64x64, K=256) ==========
        // dB staging (sig blocks)
        if (!is_mu) {
            int rr = t >> 2, c = (t & 3) * 8;
            const float* src = &Bin[(size_t)(b0g + rr) * ((NUMS + 1) * DIM)
                                    + (size_t)(j + 1) * DIM + c];
            float4 v0 = *(const float4*)src;
            float4 v1 = *(const float4*)(src + 4);
            if (j > 0) {
                float4 u0 = *(const float4*)(src - DIM);
                float4 u1 = *(const float4*)(src - DIM + 4);
                v0.x -= u0.x; v0.y -= u0.y; v0.z -= u0.z; v0.w -= u0.w;
                v1.x -= u1.x; v1.y -= u1.y; v1.z -= u1.z; v1.w -= u1.w;
            }
            *(float4*)&dBsS[rr * 36 + c] = v0;
            *(float4*)&dBsS[rr * 36 + c + 4] = v1;
        }
        // H tile staging: [64 batch x 256 k] -> HsT[k][batch], conflict-free
        {
            int rr = t >> 2, klo = (t & 3) * 4;
            #pragma unroll 4
            for (int it = 0; it < 16; ++it) {
                int k4 = klo + 16 * it;
                float4 v = __ldcg((const float4*)&d_H[(b0g + rr) * 512 + hofs + k4]);
                HsT[(k4 + 0) * HT + rr] = v.x;
                HsT[(k4 + 1) * HT + rr] = v.y;
                HsT[(k4 + 2) * HT + rr] = v.z;
                HsT[(k4 + 3) * HT + rr] = v.w;
            }
        }
        __syncthreads();

        ull acc2[2][4];
        #pragma unroll
        for (int i = 0; i < 2; ++i)
            #pragma unroll
            for (int q = 0; q < 4; ++q) acc2[i][q] = 0ull;

        for (int k8 = 0; k8 < 32; ++k8) {
            #pragma unroll
            for (int kq = 0; kq < 8; ++kq) {
                int kk = k8 * 8 + kq;
                float2 av = *(const float2*)&HsT[kk * HT + r0];
                ulonglong2 w01 = *(const ulonglong2*)&WsS[kk * WT + c0];
                ulonglong2 w23 = *(const ulonglong2*)&WsS[kk * WT + c0 + 4];
                ull a0, a1;
                asm("mov.b64 %0, {%1, %1};" : "=l"(a0) : "f"(av.x));
                asm("mov.b64 %0, {%1, %1};" : "=l"(a1) : "f"(av.y));
                fma2(acc2[0][0], a0, w01.x); fma2(acc2[0][1], a0, w01.y);
                fma2(acc2[0][2], a0, w23.x); fma2(acc2[0][3], a0, w23.y);
                fma2(acc2[1][0], a1, w01.x); fma2(acc2[1][1], a1, w01.y);
                fma2(acc2[1][2], a1, w23.x); fma2(acc2[1][3], a1, w23.y);
            }
        }

        float C[2][8];
        #pragma unroll
        for (int i = 0; i < 2; ++i) {
            asm("mov.b64 {%0, %1}, %2;" : "=f"(C[i][0]), "=f"(C[i][1]) : "l"(acc2[i][0]));
            asm("mov.b64 {%0, %1}, %2;" : "=f"(C[i][2]), "=f"(C[i][3]) : "l"(acc2[i][1]));
            asm("mov.b64 {%0, %1}, %2;" : "=f"(C[i][4]), "=f"(C[i][5]) : "l"(acc2[i][2]));
            asm("mov.b64 {%0, %1}, %2;" : "=f"(C[i][6]), "=f"(C[i][7]) : "l"(acc2[i][3]));
        }
        float bb[8] = {bs0.x, bs0.y, bs0.z, bs0.w, bs1.x, bs1.y, bs1.z, bs1.w};

        if (is_mu) {
            #pragma unroll
            for (int i = 0; i < 2; ++i) {
                float4 o0 = make_float4(C[i][0] + bb[0], C[i][1] + bb[1],
                                        C[i][2] + bb[2], C[i][3] + bb[3]);
                float4 o1 = make_float4(C[i][4] + bb[4], C[i][5] + bb[5],
                                        C[i][6] + bb[6], C[i][7] + bb[7]);
                float* dst = &d_muh[(size_t)j * (BATCH * HCH) + (b0g + r0 + i) * HCH + c0];
                *(float4*)dst = o0;
                *(float4*)(dst + 4) = o1;
            }
        } else {
            int hh = cb * 2 + wc;
            #pragma unroll
            for (int i = 0; i < 2; ++i) {
                const float* db = &dBsS[(r0 + i) * 36 + lc * 8];
                float s = 0.f;
                #pragma unroll
                for (int q = 0; q < 8; ++q) s += (C[i][q] + bb[q]) * db[q];
                s += __shfl_xor_sync(0xffffffffu, s, 1);
                s += __shfl_xor_sync(0xffffffffu, s, 2);
                if (lc == 0)
                    d_svh[(size_t)j * (BATCH * HCH) + (b0g + r0 + i) * HCH + hh] = s;
            }
        }
        gbar(target += GRID);
    }

    // ---- final output row 128 (conv only) ----
    if (bk < 128) {
        if (t < 128) { kwv[t] = DT * d_kmu[NUMS - t]; ksv[t] = d_ksig[NUMS - t]; }
        __syncthreads();
        int e = t & 127, p = t >> 7;
        float acc = 0.f;
        int base = convb0 * HCH + e;
        #pragma unroll 4
        for (int m = p; m < NUMS; m += 2)
            acc += kwv[m] * d_muh[m * (BATCH * HCH) + base]
                 + ksv[m] * d_svh[m * (BATCH * HCH) + base];
        red[t] = acc;
        __syncthreads();
        if (t < 128) {
            float s = red[t] + red[t + 128];
            float z = z0[convb0 * HCH + t];
            out[(size_t)NUMS * (BATCH * HCH) + convb0 * HCH + t] = z * d_gvals[NUMS] + s;
        }
    }
}

// ---------------- launch ----------------
extern "C" void kernel_launch(void* const* d_in, const int* in_sizes, int n_in,
                              void* d_out, int out_size)
{
    const float* B    = (const float*)d_in[0];
    const float* z0   = (const float*)d_in[1];
    const float* gw1  = (const float*)d_in[6];
    const float* gb1  = (const float*)d_in[7];
    const float* gw2  = (const float*)d_in[8];
    const float* gb2  = (const float*)d_in[9];
    const float* kmw1 = (const float*)d_in[10];
    const float* kmb1 = (const float*)d_in[11];
    const float* kmw2 = (const float*)d_in[12];
    const float* kmb2 = (const float*)d_in[13];
    const float* ksw1 = (const float*)d_in[14];
    const float* ksb1 = (const float*)d_in[15];
    const float* ksw2 = (const float*)d_in[16];
    const float* ksb2 = (const float*)d_in[17];
    const float* muw1 = (const float*)d_in[18];
    const float* mub1 = (const float*)d_in[19];
    const float* muw2 = (const float*)d_in[20];
    const float* mub2 = (const float*)d_in[21];
    const float* sgw1 = (const float*)d_in[22];
    const float* sgb1 = (const float*)d_in[23];
    const float* sgw2 = (const float*)d_in[24];
    const float* sgb2 = (const float*)d_in[25];
    float* out = (float*)d_out;

    static int smem_set = 0;
    size_t smem_bytes = SMEM_FLOATS * sizeof(float);
    if (!smem_set) {
        cudaFuncSetAttribute(solve, cudaFuncAttributeMaxDynamicSharedMemorySize,
                             (int)smem_bytes);
        smem_set = 1;
    }

    init_kernel<<<1, 256>>>(gw1, gb1, gw2, gb2, kmw1, kmb1, kmw2, kmb2,
                            ksw1, ksb1, ksw2, ksb2);
    solve<<<GRID, TPB, smem_bytes>>>(B, z0, muw1, mub1, muw2, mub2,
                                     sgw1, sgb1, sgw2, sgb2, out);
}

// round 5
// speedup vs baseline: 3.6293x; 1.4629x over previous
#include <cuda_runtime.h>
#include <cuda_bf16.h>
#include <math.h>
#include <stdint.h>

#define NUMS  128
#define BATCH 256
#define HCH   64
#define DIM   32
#define HID   256
#define XDIM  65
#define KW    32
#define DT    (1.0f/128.0f)
#define GRID  132
#define TPB   256

#define AP_B 528            // A smem row stride in bytes (264 bf16)

// smem byte offsets
#define OFF_AHI  0                       // 64 x 264 bf16 = 33792
#define OFF_ALO  33792
#define OFF_OS   67584                   // 64 x 68 f32 = 17408
#define OFF_DB   84992                   // 64 x 33 f32 = 8448
#define OFF_BIAS 93440                   // 64 f32
#define OFF_XS   93696                   // 2 x 65 f32 (pad)
#define OFF_KWV  94224                   // 128 f32
#define OFF_KSV  94736                   // 128 f32
#define OFF_RED  95248                   // 256 f32
#define SMEM_BYTES 96272

// ---------------- device scratch ----------------
__device__ float d_gvals[NUMS + 1];
__device__ float d_kmu[NUMS + 1];
__device__ float d_ksig[NUMS + 1];
__device__ uint4 d_Hhi4[BATCH * 64];    // 256 rows x 512 bf16-hi (u32-packed pairs)
__device__ uint4 d_Hlo4[BATCH * 64];    // bf16-lo
__device__ float d_muh[NUMS * BATCH * HCH];
__device__ float d_svh[NUMS * BATCH * HCH];
__device__ unsigned d_bar;

// ---------------- init ----------------
__global__ void init_kernel(const float* gw1, const float* gb1, const float* gw2, const float* gb2,
                            const float* mw1, const float* mb1, const float* mw2, const float* mb2,
                            const float* sw1, const float* sb1, const float* sw2, const float* sb2)
{
    int t = threadIdx.x;
    if (t == 0) d_bar = 0u;
    if (t <= NUMS) {
        float tt = t * DT;
        float a = gb2[0], b = mb2[0], c = sb2[0];
        for (int k = 0; k < KW; ++k) {
            a += tanhf(tt * gw1[k] + gb1[k]) * gw2[k];
            b += tanhf(tt * mw1[k] + mb1[k]) * mw2[k];
            c += tanhf(tt * sw1[k] + sb1[k]) * sw2[k];
        }
        d_gvals[t] = a; d_kmu[t] = b; d_ksig[t] = c;
    }
}

// ---------------- helpers ----------------
static __device__ __forceinline__ uint32_t s2u(const void* p) {
    uint32_t a;
    asm("{ .reg .u64 t; cvta.to.shared.u64 t, %1; cvt.u32.u64 %0, t; }" : "=r"(a) : "l"(p));
    return a;
}
static __device__ __forceinline__ void gbar(unsigned target) {
    __syncthreads();
    if (threadIdx.x == 0) {
        unsigned* p = &d_bar;
        asm volatile("red.release.gpu.global.add.u32 [%0], 1;" :: "l"(p) : "memory");
        unsigned v;
        do {
            asm volatile("ld.acquire.gpu.global.u32 %0, [%1];" : "=r"(v) : "l"(p) : "memory");
        } while ((int)(v - target) < 0);
    }
    __syncthreads();
}
static __device__ __forceinline__ void ldsm4(uint32_t addr, uint32_t* r) {
    asm volatile("ldmatrix.sync.aligned.m8n8.x4.shared.b16 {%0,%1,%2,%3}, [%4];"
                 : "=r"(r[0]), "=r"(r[1]), "=r"(r[2]), "=r"(r[3]) : "r"(addr));
}
static __device__ __forceinline__ void mma16816(float* c, const uint32_t* a,
                                                uint32_t b0, uint32_t b1) {
    asm volatile("mma.sync.aligned.m16n8k16.row.col.f32.bf16.bf16.f32 "
                 "{%0,%1,%2,%3}, {%4,%5,%6,%7}, {%8,%9}, {%0,%1,%2,%3};"
                 : "+f"(c[0]), "+f"(c[1]), "+f"(c[2]), "+f"(c[3])
                 : "r"(a[0]), "r"(a[1]), "r"(a[2]), "r"(a[3]), "r"(b0), "r"(b1));
}
static __device__ __forceinline__ unsigned packbf(float x, float y) {
    __nv_bfloat16 bx = __float2bfloat16(x), by = __float2bfloat16(y);
    return ((unsigned)__bfloat16_as_ushort(by) << 16) | __bfloat16_as_ushort(bx);
}

// ---------------- persistent solver ----------------
__global__ void __launch_bounds__(TPB, 1) solve(
    const float* __restrict__ Bin, const float* __restrict__ z0,
    const float* __restrict__ muw1, const float* __restrict__ mub1,
    const float* __restrict__ muw2, const float* __restrict__ mub2,
    const float* __restrict__ sgw1, const float* __restrict__ sgb1,
    const float* __restrict__ sgw2, const float* __restrict__ sgb2,
    float* __restrict__ out)
{
    extern __shared__ __align__(16) char sm[];
    uint32_t smb = s2u(sm);
    float* Osm   = (float*)(sm + OFF_OS);
    float* dBs   = (float*)(sm + OFF_DB);
    float* biasS = (float*)(sm + OFF_BIAS);
    float* xs    = (float*)(sm + OFF_XS);
    float* kwv   = (float*)(sm + OFF_KWV);
    float* ksv   = (float*)(sm + OFF_KSV);
    float* red   = (float*)(sm + OFF_RED);

    int bk = blockIdx.x, t = threadIdx.x;
    int wid = t >> 5, lane = t & 31;
    unsigned target = 0;

    bool is_sig = (bk < 128);
    int b0g  = is_sig ? (bk >> 5) * 64 : (bk - 128) * 64;
    int cb   = is_sig ? (bk & 31) : 0;
    int col0 = cb * 64;
    const float* W2  = is_sig ? sgw2 : muw2;
    const float* B2b = is_sig ? (sgb2 + col0) : mub2;
    int ldw   = is_sig ? (HCH * DIM) : HCH;
    int hofs4 = is_sig ? 32 : 0;

    if (t < 64) biasS[t] = B2b[t];

    // ---- B fragments (W2 slice) in registers, hi/lo, loaded ONCE ----
    int wc = wid & 3, wr = wid >> 2;          // warp: 4 col-groups x 2 row-groups
    unsigned Bhi[16][2][2], Blo[16][2][2];
    {
        int nb = col0 + wc * 16 + (lane >> 2);
        #pragma unroll
        for (int kt = 0; kt < 16; ++kt)
            #pragma unroll
            for (int nt = 0; nt < 2; ++nt)
                #pragma unroll
                for (int rr = 0; rr < 2; ++rr) {
                    int k0 = kt * 16 + (lane & 3) * 2 + rr * 8;
                    int n  = nb + nt * 8;
                    float w0 = W2[(size_t)k0 * ldw + n];
                    float w1 = W2[(size_t)(k0 + 1) * ldw + n];
                    __nv_bfloat16 h0 = __float2bfloat16(w0);
                    __nv_bfloat16 h1 = __float2bfloat16(w1);
                    float l0 = w0 - __bfloat162float(h0);
                    float l1 = w1 - __bfloat162float(h1);
                    Bhi[kt][nt][rr] = ((unsigned)__bfloat16_as_ushort(h1) << 16)
                                    | __bfloat16_as_ushort(h0);
                    Blo[kt][nt][rr] = packbf(l0, l1);
                }
    }

    int convb0 = bk * 2;
    uint32_t aBaseHi = smb + OFF_AHI + (wr * 32 + (lane & 15)) * AP_B + ((lane >> 4) * 8) * 2;
    uint32_t aBaseLo = aBaseHi + (OFF_ALO - OFF_AHI);

    for (int j = 0; j < NUMS; ++j) {
        // ========== phase 1: conv -> S_j, MLP1 -> packed hi/lo H ==========
        if (is_sig) {
            if (t < j) { kwv[t] = DT * d_kmu[j - t]; ksv[t] = d_ksig[j - t]; }
            if (t < 2) xs[t * XDIM] = j * DT;
            __syncthreads();

            int e = t & 127, p = t >> 7;
            float acc = 0.f;
            int base = convb0 * HCH + e;
            #pragma unroll 4
            for (int m = p; m < j; m += 2)
                acc += kwv[m] * d_muh[m * (BATCH * HCH) + base]
                     + ksv[m] * d_svh[m * (BATCH * HCH) + base];
            red[t] = acc;
            __syncthreads();

            if (t < 128) {
                float s = red[t] + red[t + 128];
                float z = z0[convb0 * HCH + t];
                float S = z * d_gvals[j] + s;
                out[(size_t)j * (BATCH * HCH) + convb0 * HCH + t] = S;
                xs[(t >> 6) * XDIM + 1 + (t & 63)] = (j == 0) ? z : S;
            }
            __syncthreads();

            // MLP1: row r, 4 cols of combined 512 hidden
            int r = t >> 7, ci = t & 127, c4 = ci * 4;
            const float* w1; const float* b1; int cc;
            if (c4 < 256) { w1 = muw1; b1 = mub1; cc = c4; }
            else          { w1 = sgw1; b1 = sgb1; cc = c4 - 256; }
            float4 a = *(const float4*)&b1[cc];
            #pragma unroll 5
            for (int i = 0; i < XDIM; ++i) {
                float4 wv = *(const float4*)&w1[i * HID + cc];
                float xv = xs[r * XDIM + i];
                a.x += xv * wv.x; a.y += xv * wv.y; a.z += xv * wv.z; a.w += xv * wv.w;
            }
            float v0 = tanhf(a.x), v1 = tanhf(a.y), v2 = tanhf(a.z), v3 = tanhf(a.w);
            __nv_bfloat16 h0 = __float2bfloat16(v0), h1 = __float2bfloat16(v1);
            __nv_bfloat16 h2 = __float2bfloat16(v2), h3 = __float2bfloat16(v3);
            uint2 hp, lp;
            hp.x = ((unsigned)__bfloat16_as_ushort(h1) << 16) | __bfloat16_as_ushort(h0);
            hp.y = ((unsigned)__bfloat16_as_ushort(h3) << 16) | __bfloat16_as_ushort(h2);
            lp.x = packbf(v0 - __bfloat162float(h0), v1 - __bfloat162float(h1));
            lp.y = packbf(v2 - __bfloat162float(h2), v3 - __bfloat162float(h3));
            int rowi = (convb0 + r) * 256 + ci * 2;
            *(uint2*)((unsigned*)d_Hhi4 + rowi) = hp;
            *(uint2*)((unsigned*)d_Hlo4 + rowi) = lp;
        }
        gbar(target += GRID);

        // ========== phase 2: HMMA GEMM (64 rows x 64 cols, K=256) ==========
        if (is_sig) {   // dB staging
            int row = t >> 2, c = (t & 3) * 8;
            const float* src = &Bin[(size_t)(b0g + row) * ((NUMS + 1) * DIM)
                                    + (size_t)(j + 1) * DIM + c];
            float4 v0 = *(const float4*)src;
            float4 v1 = *(const float4*)(src + 4);
            if (j > 0) {
                float4 u0 = *(const float4*)(src - DIM);
                float4 u1 = *(const float4*)(src - DIM + 4);
                v0.x -= u0.x; v0.y -= u0.y; v0.z -= u0.z; v0.w -= u0.w;
                v1.x -= u1.x; v1.y -= u1.y; v1.z -= u1.z; v1.w -= u1.w;
            }
            dBs[row * 33 + c + 0] = v0.x; dBs[row * 33 + c + 1] = v0.y;
            dBs[row * 33 + c + 2] = v0.z; dBs[row * 33 + c + 3] = v0.w;
            dBs[row * 33 + c + 4] = v1.x; dBs[row * 33 + c + 5] = v1.y;
            dBs[row * 33 + c + 6] = v1.z; dBs[row * 33 + c + 7] = v1.w;
        }
        {   // A staging: H tile [64 x 256] hi+lo bf16 -> smem
            int row = t & 63, part = t >> 6;       // 0..3
            int isLo = part >> 1, half = part & 1;
            const uint4* src = (isLo ? d_Hlo4 : d_Hhi4)
                               + (b0g + row) * 64 + hofs4 + half * 16;
            char* dst = sm + (isLo ? OFF_ALO : OFF_AHI) + row * AP_B + half * 256;
            #pragma unroll 4
            for (int it = 0; it < 16; ++it) {
                uint4 v = __ldcg(src + it);
                *(uint4*)(dst + it * 16) = v;
            }
        }
        __syncthreads();

        float acc[2][2][4];
        #pragma unroll
        for (int mt = 0; mt < 2; ++mt)
            #pragma unroll
            for (int nt = 0; nt < 2; ++nt)
                #pragma unroll
                for (int q = 0; q < 4; ++q) acc[mt][nt][q] = 0.f;

        #pragma unroll
        for (int kt = 0; kt < 16; ++kt) {
            uint32_t ah[2][4], al[2][4];
            #pragma unroll
            for (int mt = 0; mt < 2; ++mt) {
                ldsm4(aBaseHi + mt * (16 * AP_B) + kt * 32, ah[mt]);
                ldsm4(aBaseLo + mt * (16 * AP_B) + kt * 32, al[mt]);
            }
            #pragma unroll
            for (int mt = 0; mt < 2; ++mt)
                #pragma unroll
                for (int nt = 0; nt < 2; ++nt) {
                    mma16816(acc[mt][nt], ah[mt], Bhi[kt][nt][0], Bhi[kt][nt][1]);
                    mma16816(acc[mt][nt], ah[mt], Blo[kt][nt][0], Blo[kt][nt][1]);
                    mma16816(acc[mt][nt], al[mt], Bhi[kt][nt][0], Bhi[kt][nt][1]);
                }
        }

        // ---- epilogue: O tile to smem (+bias) ----
        __syncthreads();   // dBs/A-smem fully consumed; Osm overlaps nothing live
        {
            int rb = wr * 32 + (lane >> 2);
            int cbc = wc * 16 + (lane & 3) * 2;
            #pragma unroll
            for (int mt = 0; mt < 2; ++mt)
                #pragma unroll
                for (int nt = 0; nt < 2; ++nt) {
                    int row0 = rb + mt * 16, col = cbc + nt * 8;
                    Osm[row0 * 68 + col]       = acc[mt][nt][0] + biasS[col];
                    Osm[row0 * 68 + col + 1]   = acc[mt][nt][1] + biasS[col + 1];
                    Osm[(row0 + 8) * 68 + col]     = acc[mt][nt][2] + biasS[col];
                    Osm[(row0 + 8) * 68 + col + 1] = acc[mt][nt][3] + biasS[col + 1];
                }
        }
        __syncthreads();

        if (is_sig) {
            if (t < 128) {
                int row = t >> 1, hh = t & 1;
                const float* orow = &Osm[row * 68 + hh * 32];
                const float* drow = &dBs[row * 33];
                float s = 0.f;
                #pragma unroll 8
                for (int d = 0; d < 32; ++d) s = fmaf(orow[d], drow[d], s);
                d_svh[(size_t)j * (BATCH * HCH) + (b0g + row) * HCH + cb * 2 + hh] = s;
            }
        } else {
            int row = t >> 2, c0m = (t & 3) * 16;
            float* dst = &d_muh[(size_t)j * (BATCH * HCH) + (b0g + row) * HCH + c0m];
            #pragma unroll
            for (int q = 0; q < 4; ++q)
                *(float4*)(dst + q * 4) = *(const float4*)&Osm[row * 68 + c0m + q * 4];
        }
        gbar(target += GRID);
    }

    // ---- final output row 128 (conv only) ----
    if (is_sig) {
        if (t < 128) { kwv[t] = DT * d_kmu[NUMS - t]; ksv[t] = d_ksig[NUMS - t]; }
        __syncthreads();
        int e = t & 127, p = t >> 7;
        float acc = 0.f;
        int base = convb0 * HCH + e;
        #pragma unroll 4
        for (int m = p; m < NUMS; m += 2)
            acc += kwv[m] * d_muh[m * (BATCH * HCH) + base]
                 + ksv[m] * d_svh[m * (BATCH * HCH) + base];
        red[t] = acc;
        __syncthreads();
        if (t < 128) {
            float s = red[t] + red[t + 128];
            float z = z0[convb0 * HCH + t];
            out[(size_t)NUMS * (BATCH * HCH) + convb0 * HCH + t] = z * d_gvals[NUMS] + s;
        }
    }
}

// ---------------- launch ----------------
extern "C" void kernel_launch(void* const* d_in, const int* in_sizes, int n_in,
                              void* d_out, int out_size)
{
    const float* B    = (const float*)d_in[0];
    const float* z0   = (const float*)d_in[1];
    const float* gw1  = (const float*)d_in[6];
    const float* gb1  = (const float*)d_in[7];
    const float* gw2  = (const float*)d_in[8];
    const float* gb2  = (const float*)d_in[9];
    const float* kmw1 = (const float*)d_in[10];
    const float* kmb1 = (const float*)d_in[11];
    const float* kmw2 = (const float*)d_in[12];
    const float* kmb2 = (const float*)d_in[13];
    const float* ksw1 = (const float*)d_in[14];
    const float* ksb1 = (const float*)d_in[15];
    const float* ksw2 = (const float*)d_in[16];
    const float* ksb2 = (const float*)d_in[17];
    const float* muw1 = (const float*)d_in[18];
    const float* mub1 = (const float*)d_in[19];
    const float* muw2 = (const float*)d_in[20];
    const float* mub2 = (const float*)d_in[21];
    const float* sgw1 = (const float*)d_in[22];
    const float* sgb1 = (const float*)d_in[23];
    const float* sgw2 = (const float*)d_in[24];
    const float* sgb2 = (const float*)d_in[25];
    float* out = (float*)d_out;

    static int smem_set = 0;
    if (!smem_set) {
        cudaFuncSetAttribute(solve, cudaFuncAttributeMaxDynamicSharedMemorySize, SMEM_BYTES);
        smem_set = 1;
    }

    init_kernel<<<1, 256>>>(gw1, gb1, gw2, gb2, kmw1, kmb1, kmw2, kmb2,
                            ksw1, ksb1, ksw2, ksb2);
    solve<<<GRID, TPB, SMEM_BYTES>>>(B, z0, muw1, mub1, muw2, mub2,
                                     sgw1, sgb1, sgw2, sgb2, out);
}